// round 4
// baseline (speedup 1.0000x reference)
#include <cuda_runtime.h>
#include <math.h>

#define NROWS   65536
#define DIMK    64
#define CB      1024
#define TOPKK   3
#define THREADS 128
#define NBLOCKS 512
#define CHUNK   128
#define NCHUNK  8
#define EPAD    68        // padded row stride (floats): 272B, 16B-aligned, bank-delta 4

// Output layout (concatenated reference tuple, fp32):
//   z_q_st [4194304] | loss [1] | perplexity [1] | encodings [201326592] | idx [196608]
#define OFF_LOSS 4194304ull
#define OFF_PERP 4194305ull
#define OFF_ENC  4194306ull   // byte offset % 16 == 8 -> only 8B-aligned; float2 stores
#define OFF_IDX  205520898ull

// Self-cleaning device state (zero-init at load; finisher re-zeroes after use)
__device__ unsigned int g_hist[CB];
__device__ float        g_blk_loss[NBLOCKS];
__device__ unsigned int g_done;

// smem layout (floats)
#define SM_Z    0
#define SM_E    (128 * EPAD)
#define SM_ZSQ  (2 * 128 * EPAD)
#define SM_ESQ  (SM_ZSQ + 128)
#define SM_TIDX (SM_ESQ + 128)         // 128*3 ints
#define SM_RED  (SM_TIDX + 384)
#define SM_TOT  (SM_RED + 32)
#define SMEM_BYTES (SM_TOT * 4)

__device__ __forceinline__ void unpack2(unsigned long long u, float& lo, float& hi) {
    asm("mov.b64 {%0, %1}, %2;" : "=f"(lo), "=f"(hi) : "l"(u));
}
__device__ __forceinline__ unsigned long long ffma2(unsigned long long a, unsigned long long b,
                                                    unsigned long long c) {
    unsigned long long d;
    asm("fma.rn.f32x2 %0, %1, %2, %3;" : "=l"(d) : "l"(a), "l"(b), "l"(c));
    return d;
}

// insert (d, gi) into sorted triple, lexicographic (d, idx) order (tie -> lower idx)
__device__ __forceinline__ void ins3(float d, int gi,
                                     float& s0, float& s1, float& s2,
                                     int& i0, int& i1, int& i2) {
    if (d < s2 || (d == s2 && gi < i2)) {
        if (d < s1 || (d == s1 && gi < i1)) {
            s2 = s1; i2 = i1;
            if (d < s0 || (d == s0 && gi < i0)) { s1 = s0; i1 = i0; s0 = d; i0 = gi; }
            else                                { s1 = d;  i1 = gi; }
        } else { s2 = d; i2 = gi; }
    }
}

__global__ void __launch_bounds__(THREADS) vq_fused(
    const float* __restrict__ z, const float* __restrict__ emb, float* __restrict__ out)
{
    extern __shared__ float sm[];
    float* zbuf  = sm + SM_Z;
    float* ebuf  = sm + SM_E;
    float* zsq_s = sm + SM_ZSQ;
    float* esq_s = sm + SM_ESQ;
    int*   tidx  = (int*)(sm + SM_TIDX);
    float* red   = sm + SM_RED;
    __shared__ unsigned int is_last;

    const int t    = threadIdx.x;
    const int b    = blockIdx.x;
    const int lane = t & 31;
    const int w    = t >> 5;
    const int rg   = lane >> 2;   // row group 0..7
    const int cg   = lane & 3;    // code group 0..3

    // ---- stage z rows (128 per block) into padded smem; fold |z|^2 ----
    {
        const float4* zr  = (const float4*)(z + (size_t)(b * THREADS + t) * DIMK);
        float4*       dst = (float4*)(zbuf + t * EPAD);
        float s = 0.f;
        #pragma unroll
        for (int i = 0; i < 16; i++) {
            float4 v = __ldg(zr + i);
            s += v.x*v.x; s += v.y*v.y; s += v.z*v.z; s += v.w*v.w;
            dst[i] = v;
        }
        zsq_s[t] = s;
    }
    __syncthreads();

    // this thread's 4 rows (interleaved: conflict-free smem loads)
    int   zoff[4]; float zsqr[4];
    #pragma unroll
    for (int j = 0; j < 4; j++) {
        int lr = w * 32 + 8 * j + rg;
        zoff[j] = lr * EPAD;
        zsqr[j] = zsq_s[lr];
    }

    float s0[4], s1[4], s2[4]; int i0_[4], i1_[4], i2_[4];
    #pragma unroll
    for (int j = 0; j < 4; j++) {
        s0[j] = s1[j] = s2[j] = 3.4e38f;
        i0_[j] = i1_[j] = i2_[j] = 0;
    }

    float2* encb2 = (float2*)(out + OFF_ENC + (size_t)b * THREADS * (TOPKK * CB));

    for (int c = 0; c < NCHUNK; c++) {
        __syncthreads();
        // ---- stage codebook chunk (128 codes) + |e|^2 ----
        {
            const float4* er  = (const float4*)(emb + (size_t)(c * CHUNK + t) * DIMK);
            float4*       dst = (float4*)(ebuf + t * EPAD);
            float s = 0.f;
            #pragma unroll
            for (int i = 0; i < 16; i++) {
                float4 v = __ldg(er + i);
                s += v.x*v.x; s += v.y*v.y; s += v.z*v.z; s += v.w*v.w;
                dst[i] = v;
            }
            esq_s[t] = s;
        }
        __syncthreads();

        // ---- interleaved coalesced zeroing of 1/8 of this block's one-hot region ----
        {
            const float2 zz = make_float2(0.f, 0.f);
            float2* d2 = encb2 + (size_t)c * 24576;
            #pragma unroll 8
            for (int i = 0; i < 192; i++) d2[i * THREADS + t] = zz;
        }

        // ---- register-tiled distance passes: 32 codes per pass, 4 passes ----
        for (int p = 0; p < 4; p++) {
            const float* ebase = ebuf + (p * 32 + cg) * EPAD;
            unsigned long long acc[4][8];
            #pragma unroll
            for (int j = 0; j < 4; j++)
                #pragma unroll
                for (int i = 0; i < 8; i++) acc[j][i] = 0ull;

            #pragma unroll
            for (int k = 0; k < DIMK; k += 4) {
                ulonglong2 zj[4];
                #pragma unroll
                for (int j = 0; j < 4; j++)
                    zj[j] = *(const ulonglong2*)(zbuf + zoff[j] + k);
                #pragma unroll
                for (int i = 0; i < 8; i++) {
                    ulonglong2 e = *(const ulonglong2*)(ebase + i * 4 * EPAD + k);
                    #pragma unroll
                    for (int j = 0; j < 4; j++) {
                        acc[j][i] = ffma2(zj[j].x, e.x, acc[j][i]);
                        acc[j][i] = ffma2(zj[j].y, e.y, acc[j][i]);
                    }
                }
            }

            #pragma unroll
            for (int i = 0; i < 8; i++) {
                int   cl = p * 32 + 4 * i + cg;
                float es = esq_s[cl];
                int   gi = c * CHUNK + cl;
                #pragma unroll
                for (int j = 0; j < 4; j++) {
                    float lo, hi; unpack2(acc[j][i], lo, hi);
                    float d = __fsub_rn(__fadd_rn(zsqr[j], es),
                                        __fmul_rn(2.0f, __fadd_rn(lo, hi)));
                    ins3(d, gi, s0[j], s1[j], s2[j], i0_[j], i1_[j], i2_[j]);
                }
            }
        }
    }

    // ---- merge top-3 across the 4 code-group lanes (xor 1, then 2) ----
    #pragma unroll
    for (int j = 0; j < 4; j++) {
        #pragma unroll
        for (int off = 1; off <= 2; off <<= 1) {
            float d0 = __shfl_xor_sync(0xffffffffu, s0[j], off);
            float d1 = __shfl_xor_sync(0xffffffffu, s1[j], off);
            float d2 = __shfl_xor_sync(0xffffffffu, s2[j], off);
            int   a0 = __shfl_xor_sync(0xffffffffu, i0_[j], off);
            int   a1 = __shfl_xor_sync(0xffffffffu, i1_[j], off);
            int   a2 = __shfl_xor_sync(0xffffffffu, i2_[j], off);
            ins3(d0, a0, s0[j], s1[j], s2[j], i0_[j], i1_[j], i2_[j]);
            ins3(d1, a1, s0[j], s1[j], s2[j], i0_[j], i1_[j], i2_[j]);
            ins3(d2, a2, s0[j], s1[j], s2[j], i0_[j], i1_[j], i2_[j]);
        }
        if (cg == 0) {
            int lr = w * 32 + 8 * j + rg;
            tidx[lr * 3 + 0] = i0_[j];
            tidx[lr * 3 + 1] = i1_[j];
            tidx[lr * 3 + 2] = i2_[j];
        }
    }
    __syncthreads();

    // ---- epilogue: thread t owns local row t ----
    const int row = b * THREADS + t;
    const int a0 = tidx[t * 3 + 0], a1 = tidx[t * 3 + 1], a2 = tidx[t * 3 + 2];
    {
        const float4* e0 = (const float4*)(emb + (size_t)a0 * DIMK);
        const float4* e1 = (const float4*)(emb + (size_t)a1 * DIMK);
        const float4* e2 = (const float4*)(emb + (size_t)a2 * DIMK);
        const float4* zr = (const float4*)(zbuf + t * EPAD);
        float4* zqout = (float4*)(out + (size_t)row * DIMK);
        float ls = 0.f;
        #pragma unroll
        for (int i = 0; i < 16; i++) {
            float4 v0 = __ldg(e0 + i), v1 = __ldg(e1 + i), v2 = __ldg(e2 + i);
            float4 zv = zr[i];
            float4 q;
            q.x = __fdiv_rn(__fadd_rn(__fadd_rn(v0.x, v1.x), v2.x), 3.0f);
            q.y = __fdiv_rn(__fadd_rn(__fadd_rn(v0.y, v1.y), v2.y), 3.0f);
            q.z = __fdiv_rn(__fadd_rn(__fadd_rn(v0.z, v1.z), v2.z), 3.0f);
            q.w = __fdiv_rn(__fadd_rn(__fadd_rn(v0.w, v1.w), v2.w), 3.0f);
            float dx = q.x - zv.x; ls += dx*dx;
            dx = q.y - zv.y; ls += dx*dx;
            dx = q.z - zv.z; ls += dx*dx;
            dx = q.w - zv.w; ls += dx*dx;
            zqout[i] = q;   // straight-through: z_q_st == z_q numerically
        }
        int idxs[3] = { a0, a1, a2 };
        #pragma unroll
        for (int s = 0; s < TOPKK; s++) {
            out[OFF_IDX + (size_t)row * TOPKK + s] = (float)idxs[s];
            out[OFF_ENC + (size_t)row * (TOPKK * CB) + (size_t)s * CB + idxs[s]] = 1.0f;
            atomicAdd(&g_hist[idxs[s]], 1u);
        }
        // block loss reduction (deterministic tree)
        #pragma unroll
        for (int off = 16; off > 0; off >>= 1)
            ls += __shfl_xor_sync(0xffffffffu, ls, off);
        if (lane == 0) red[w] = ls;
    }
    __syncthreads();
    if (t == 0) {
        g_blk_loss[b] = red[0] + red[1] + red[2] + red[3];
        __threadfence();
        unsigned int k = atomicAdd(&g_done, 1u);
        is_last = (k == NBLOCKS - 1) ? 1u : 0u;
    }
    __syncthreads();

    // ---- finisher: last block computes loss & perplexity, re-zeroes state ----
    if (is_last) {
        __threadfence();
        float term = 0.f;
        #pragma unroll
        for (int i = 0; i < 8; i++) {
            unsigned int h = g_hist[t * 8 + i];
            float pp = (float)h * (1.0f / 196608.0f);
            term += pp * logf(pp + 1e-10f);
            g_hist[t * 8 + i] = 0u;           // self-clean for next replay
        }
        float lsum = 0.f;
        #pragma unroll
        for (int i = 0; i < 4; i++) lsum += g_blk_loss[t * 4 + i];
        #pragma unroll
        for (int off = 16; off > 0; off >>= 1) {
            term += __shfl_xor_sync(0xffffffffu, term, off);
            lsum += __shfl_xor_sync(0xffffffffu, lsum, off);
        }
        if (lane == 0) { red[w] = term; red[8 + w] = lsum; }
        __syncthreads();
        if (t == 0) {
            float tt = red[0] + red[1] + red[2] + red[3];
            float ll = red[8] + red[9] + red[10] + red[11];
            float m  = ll * (1.0f / 4194304.0f);
            out[OFF_LOSS] = __fadd_rn(__fmul_rn(0.25f, m), m);   // beta*m + m
            out[OFF_PERP] = expf(-tt);
            g_done = 0u;                      // self-clean
        }
    }
}

extern "C" void kernel_launch(void* const* d_in, const int* in_sizes, int n_in,
                              void* d_out, int out_size) {
    const float* z   = (const float*)d_in[0];
    const float* emb = (const float*)d_in[1];
    float* out = (float*)d_out;
    (void)in_sizes; (void)n_in; (void)out_size;
    cudaFuncSetAttribute(vq_fused, cudaFuncAttributeMaxDynamicSharedMemorySize, SMEM_BYTES);
    vq_fused<<<NBLOCKS, THREADS, SMEM_BYTES>>>(z, emb, out);
}